// round 4
// baseline (speedup 1.0000x reference)
#include <cuda_runtime.h>
#include <cstdint>

#define D   768
#define DV  (D / 4)    // 192 float4 per row
#define E   8
#define RB  4          // rows per warp-batch
#define NJ  12         // k-iterations (16 float4 columns per iter)

typedef unsigned long long ull;

// packed 2-wide fp32 FMA: d = a*b + d (elementwise on 2 lanes)
__device__ __forceinline__ void ffma2(ull& d, ull a, ull b) {
    asm("fma.rn.f32x2 %0, %1, %2, %0;" : "+l"(d) : "l"(a), "l"(b));
}
// broadcast one f32 into both halves of a b64
__device__ __forceinline__ ull bcast2(float x) {
    ull r;
    asm("mov.b64 %0, {%1, %1};" : "=l"(r) : "r"(__float_as_uint(x)));
    return r;
}
#define COMP(v, c) ((c) == 0 ? (v).x : (c) == 1 ? (v).y : (c) == 2 ? (v).z : (v).w)

__global__ __launch_bounds__(256, 4)   // <=64 regs -> 32 warps/SM
void router_kernel(const float* __restrict__ h,
                   const float* __restrict__ gw,
                   const float* __restrict__ gb,
                   float* __restrict__ out, int B) {
    // w transposed+packed: ws2[(c*2+g)*DV + k4] = float4 of experts {4g..4g+3},
    // scalar column (4*k4 + c). Read as ulonglong2 -> two expert-pairs.
    __shared__ float4 ws2[8 * DV];    // 24 KB
    __shared__ float  b_sh[E];

    for (int i = threadIdx.x; i < 8 * DV; i += blockDim.x) {
        const int k4 = i % DV;
        const int cg = i / DV;        // c*2+g
        const int c  = cg >> 1;
        const int g  = cg & 1;
        const int col = 4 * k4 + c;
        ws2[i] = make_float4(gw[(4 * g + 0) * D + col],
                             gw[(4 * g + 1) * D + col],
                             gw[(4 * g + 2) * D + col],
                             gw[(4 * g + 3) * D + col]);
    }
    if (threadIdx.x < E) b_sh[threadIdx.x] = gb[threadIdx.x];
    __syncthreads();

    const ulonglong2* wsu = reinterpret_cast<const ulonglong2*>(ws2);

    const int lane   = threadIdx.x & 31;
    const int half   = lane >> 4;        // 0: rows {0,1}, 1: rows {2,3}
    const int kl     = lane & 15;        // k-slot within half-warp
    const int warp   = threadIdx.x >> 5;
    const int gwarp  = blockIdx.x * (blockDim.x >> 5) + warp;
    const int nwarps = gridDim.x * (blockDim.x >> 5);
    const int nbatch = B / RB;

    float* out_idx = out;                       // [B,2] indices (as float)
    float* out_wt  = out + (size_t)2 * B;       // [B,2] weights
    float* out_lg  = out + (size_t)4 * B;       // [B,8] logits

    const float4* h4 = reinterpret_cast<const float4*>(h);

    for (int batch = gwarp; batch < nbatch; batch += nwarps) {
        const int row0 = batch * RB;
        // this lane's 2 rows: row0 + 2*half (+0 / +1); coalesced per half-warp
        const float4* hrow = h4 + (size_t)(row0 + 2 * half) * DV + kl;

        // acc2[r][p] packs experts (2p, 2p+1) for local row r (0/1)
        ull acc2[2][4];
        #pragma unroll
        for (int r = 0; r < 2; r++)
            #pragma unroll
            for (int p = 0; p < 4; p++) acc2[r][p] = 0ull;

        // software pipeline: x for iter j in regs, iter j+1 in flight
        float4 x0 = hrow[0];
        float4 x1 = hrow[DV];

        #pragma unroll
        for (int j = 0; j < NJ; j++) {
            float4 n0, n1;
            if (j < NJ - 1) {
                n0 = hrow[(j + 1) * 16];
                n1 = hrow[(j + 1) * 16 + DV];
            }
            const int k4 = j * 16 + kl;
            #pragma unroll
            for (int c = 0; c < 4; c++) {
                // both half-warps read same addresses -> LDS broadcast
                const ulonglong2 wg0 = wsu[(c * 2 + 0) * DV + k4]; // experts 0-3
                const ulonglong2 wg1 = wsu[(c * 2 + 1) * DV + k4]; // experts 4-7
                {
                    const ull xb = bcast2(COMP(x0, c));
                    ffma2(acc2[0][0], wg0.x, xb); ffma2(acc2[0][1], wg0.y, xb);
                    ffma2(acc2[0][2], wg1.x, xb); ffma2(acc2[0][3], wg1.y, xb);
                }
                {
                    const ull xb = bcast2(COMP(x1, c));
                    ffma2(acc2[1][0], wg0.x, xb); ffma2(acc2[1][1], wg0.y, xb);
                    ffma2(acc2[1][2], wg1.x, xb); ffma2(acc2[1][3], wg1.y, xb);
                }
            }
            if (j < NJ - 1) { x0 = n0; x1 = n1; }
        }

        // unpack to 16 scalars: v[r*8 + e] for local rows r in {0,1}
        float v[16];
        #pragma unroll
        for (int r = 0; r < 2; r++)
            #pragma unroll
            for (int p = 0; p < 4; p++) {
                uint32_t lo, hi;
                asm("mov.b64 {%0, %1}, %2;" : "=r"(lo), "=r"(hi) : "l"(acc2[r][p]));
                v[r * E + 2 * p]     = __uint_as_float(lo);
                v[r * E + 2 * p + 1] = __uint_as_float(hi);
            }

        // Butterfly transpose-reduce within each 16-lane half (offsets 8..1):
        // afterwards lane l holds the full sum of local index (l & 15).
        #pragma unroll
        for (int off = 8; off >= 1; off >>= 1) {
            const bool up = (kl & off) != 0;
            #pragma unroll
            for (int i = 0; i < off; i++) {
                float send = up ? v[i] : v[i + off];
                float recv = __shfl_xor_sync(0xffffffffu, send, off);
                v[i] = (up ? v[i + off] : v[i]) + recv;
            }
        }

        // lane l -> row = row0 + (l>>3), expert e = l&7  (same map as before)
        const int e   = lane & 7;
        const int row = row0 + (lane >> 3);
        const float logit = v[0] + b_sh[e];

        out_lg[(size_t)row * E + e] = logit;     // 32 consecutive floats/warp

        // gather this row's 8 logits (group base = lane & 24)
        float lv[8];
        #pragma unroll
        for (int k = 0; k < 8; k++)
            lv[k] = __shfl_sync(0xffffffffu, logit, (lane & 24) | k);

        if (e == 0) {
            // top-1: strict >, lowest index wins ties (matches lax.top_k)
            int i1 = 0; float v1 = lv[0];
            #pragma unroll
            for (int k = 1; k < 8; k++)
                if (lv[k] > v1) { v1 = lv[k]; i1 = k; }
            int i2 = (i1 == 0) ? 1 : 0; float v2 = lv[i2];
            #pragma unroll
            for (int k = 0; k < 8; k++)
                if (k != i1 && lv[k] > v2) { v2 = lv[k]; i2 = k; }

            const float t  = __expf(v2 - v1);     // <= 1
            const float w1 = 1.0f / (1.0f + t);
            const float w2 = t * w1;

            out_idx[(size_t)row * 2]     = (float)i1;
            out_idx[(size_t)row * 2 + 1] = (float)i2;
            out_wt [(size_t)row * 2]     = w1;
            out_wt [(size_t)row * 2 + 1] = w2;
        }
    }
}

extern "C" void kernel_launch(void* const* d_in, const int* in_sizes, int n_in,
                              void* d_out, int out_size) {
    const float* h  = (const float*)d_in[0];   // [B, 768]
    const float* gw = (const float*)d_in[1];   // [8, 768]
    const float* gb = (const float*)d_in[2];   // [8]
    float* out = (float*)d_out;

    const int B = in_sizes[0] / D;             // 32768

    // 592 = 4 x 148: exactly 4 CTAs per SM in a single wave (occ 4),
    // batch imbalance (2 vs 1 per warp) spreads evenly across SMs.
    const int threads = 256;
    const int blocks  = 592;
    router_kernel<<<blocks, threads>>>(h, gw, gb, out, B);
}

// round 5
// speedup vs baseline: 5.3448x; 5.3448x over previous
#include <cuda_runtime.h>
#include <cstdint>

#define D   768
#define DV  (D / 4)    // 192 float4 per row
#define E   8
#define RB  4          // rows per warp-batch
#define NJ  12         // k-iterations (16 float4 columns per iter per half-warp)

typedef unsigned long long ull;

// packed 2-wide fp32 FMA: d = a*b + d (elementwise on 2 lanes)
__device__ __forceinline__ void ffma2(ull& d, ull a, ull b) {
    asm("fma.rn.f32x2 %0, %1, %2, %0;" : "+l"(d) : "l"(a), "l"(b));
}
// broadcast one f32 into both halves of a b64
__device__ __forceinline__ ull bcast2(float x) {
    ull r;
    asm("mov.b64 %0, {%1, %1};" : "=l"(r) : "r"(__float_as_uint(x)));
    return r;
}
#define COMP(v, c) ((c) == 0 ? (v).x : (c) == 1 ? (v).y : (c) == 2 ? (v).z : (v).w)

__global__ __launch_bounds__(256, 4)   // <=64 regs -> 32 warps/SM
void router_kernel(const float* __restrict__ h,
                   const float* __restrict__ gw,
                   const float* __restrict__ gb,
                   float* __restrict__ out, int B) {
    // w transposed+packed: ws2[(c*2+g)*DV + k4] = float4 of experts {4g..4g+3},
    // scalar column (4*k4 + c). Read as ulonglong2 -> two expert-pairs.
    __shared__ float4 ws2[8 * DV];    // 24 KB
    __shared__ float  b_sh[E];

    for (int i = threadIdx.x; i < 8 * DV; i += blockDim.x) {
        const int k4 = i % DV;
        const int cg = i / DV;        // c*2+g
        const int c  = cg >> 1;
        const int g  = cg & 1;
        const int col = 4 * k4 + c;
        ws2[i] = make_float4(gw[(4 * g + 0) * D + col],
                             gw[(4 * g + 1) * D + col],
                             gw[(4 * g + 2) * D + col],
                             gw[(4 * g + 3) * D + col]);
    }
    if (threadIdx.x < E) b_sh[threadIdx.x] = gb[threadIdx.x];
    __syncthreads();

    const ulonglong2* wsu = reinterpret_cast<const ulonglong2*>(ws2);

    const int lane   = threadIdx.x & 31;
    const int half   = lane >> 4;        // 0: rows {0,1}, 1: rows {2,3}
    const int kl     = lane & 15;        // k-slot within half-warp
    const int warp   = threadIdx.x >> 5;
    const int gwarp  = blockIdx.x * (blockDim.x >> 5) + warp;
    const int nwarps = gridDim.x * (blockDim.x >> 5);
    const int nbatch = B / RB;

    float* out_idx = out;                       // [B,2] indices (as float)
    float* out_wt  = out + (size_t)2 * B;       // [B,2] weights
    float* out_lg  = out + (size_t)4 * B;       // [B,8] logits

    const float4* h4 = reinterpret_cast<const float4*>(h);

    for (int batch = gwarp; batch < nbatch; batch += nwarps) {
        const int row0 = batch * RB;
        // this lane's 2 rows: row0 + 2*half (+0 / +1); coalesced per half-warp
        const float4* hrow = h4 + (size_t)(row0 + 2 * half) * DV + kl;

        // acc2[r][p] packs experts (2p, 2p+1) for local row r (0/1)
        ull acc2[2][4];
        #pragma unroll
        for (int r = 0; r < 2; r++)
            #pragma unroll
            for (int p = 0; p < 4; p++) acc2[r][p] = 0ull;

        // rolling double buffer: x = iter j, (n0,n1) = iter j+1 in flight
        float4 x0 = hrow[0];
        float4 x1 = hrow[DV];

        #pragma unroll 1
        for (int j = 0; j < NJ; j++) {
            // branchless clamped prefetch (last iter re-loads own tile: L1 hit)
            const int jn = (j < NJ - 1) ? (j + 1) * 16 : j * 16;
            const float4 n0 = hrow[jn];
            const float4 n1 = hrow[jn + DV];

            const int k4 = j * 16 + kl;
            #pragma unroll
            for (int c = 0; c < 4; c++) {
                // both half-warps read same addresses -> LDS broadcast
                const ulonglong2 wg0 = wsu[(c * 2 + 0) * DV + k4]; // experts 0-3
                const ulonglong2 wg1 = wsu[(c * 2 + 1) * DV + k4]; // experts 4-7
                {
                    const ull xb = bcast2(COMP(x0, c));
                    ffma2(acc2[0][0], wg0.x, xb); ffma2(acc2[0][1], wg0.y, xb);
                    ffma2(acc2[0][2], wg1.x, xb); ffma2(acc2[0][3], wg1.y, xb);
                }
                {
                    const ull xb = bcast2(COMP(x1, c));
                    ffma2(acc2[1][0], wg0.x, xb); ffma2(acc2[1][1], wg0.y, xb);
                    ffma2(acc2[1][2], wg1.x, xb); ffma2(acc2[1][3], wg1.y, xb);
                }
            }
            x0 = n0; x1 = n1;
        }

        // unpack to 16 scalars: v[r*8 + e] for local rows r in {0,1}
        float v[16];
        #pragma unroll
        for (int r = 0; r < 2; r++)
            #pragma unroll
            for (int p = 0; p < 4; p++) {
                uint32_t lo, hi;
                asm("mov.b64 {%0, %1}, %2;" : "=r"(lo), "=r"(hi) : "l"(acc2[r][p]));
                v[r * E + 2 * p]     = __uint_as_float(lo);
                v[r * E + 2 * p + 1] = __uint_as_float(hi);
            }

        // Butterfly transpose-reduce within each 16-lane half (offsets 8..1):
        // afterwards lane l holds the full sum of local index (l & 15).
        #pragma unroll
        for (int off = 8; off >= 1; off >>= 1) {
            const bool up = (kl & off) != 0;
            #pragma unroll
            for (int i = 0; i < off; i++) {
                float send = up ? v[i] : v[i + off];
                float recv = __shfl_xor_sync(0xffffffffu, send, off);
                v[i] = (up ? v[i + off] : v[i]) + recv;
            }
        }

        // lane l -> row = row0 + (l>>3), expert e = l&7
        const int e   = lane & 7;
        const int row = row0 + (lane >> 3);
        const float logit = v[0] + b_sh[e];

        out_lg[(size_t)row * E + e] = logit;     // 32 consecutive floats/warp

        // gather this row's 8 logits (group base = lane & 24)
        float lv[8];
        #pragma unroll
        for (int k = 0; k < 8; k++)
            lv[k] = __shfl_sync(0xffffffffu, logit, (lane & 24) | k);

        if (e == 0) {
            // top-1: strict >, lowest index wins ties (matches lax.top_k)
            int i1 = 0; float v1 = lv[0];
            #pragma unroll
            for (int k = 1; k < 8; k++)
                if (lv[k] > v1) { v1 = lv[k]; i1 = k; }
            int i2 = (i1 == 0) ? 1 : 0; float v2 = lv[i2];
            #pragma unroll
            for (int k = 0; k < 8; k++)
                if (k != i1 && lv[k] > v2) { v2 = lv[k]; i2 = k; }

            const float t  = __expf(v2 - v1);     // <= 1
            const float w1 = 1.0f / (1.0f + t);
            const float w2 = t * w1;

            out_idx[(size_t)row * 2]     = (float)i1;
            out_idx[(size_t)row * 2 + 1] = (float)i2;
            out_wt [(size_t)row * 2]     = w1;
            out_wt [(size_t)row * 2 + 1] = w2;
        }
    }
}

extern "C" void kernel_launch(void* const* d_in, const int* in_sizes, int n_in,
                              void* d_out, int out_size) {
    const float* h  = (const float*)d_in[0];   // [B, 768]
    const float* gw = (const float*)d_in[1];   // [8, 768]
    const float* gb = (const float*)d_in[2];   // [8]
    float* out = (float*)d_out;

    const int B = in_sizes[0] / D;             // 32768

    // 592 = 4 x 148: exactly 4 CTAs per SM in a single wave (occ 4).
    const int threads = 256;
    const int blocks  = 592;
    router_kernel<<<blocks, threads>>>(h, gw, gb, out, B);
}